// round 3
// baseline (speedup 1.0000x reference)
#include <cuda_runtime.h>

// SConv2d: 3x3 conv-shaped majority-gate network.
// out[n,oc,h,w] = maj3-tree over k=(c,kh,kw) of patch(n,c,h+kh-1,w+kw-1)*w[oc,c,kh,kw]
// with pad value -1. Tree math kept in s-domain: s=(prod+1)/2 at leaves,
// node r = ab+ac+bc-2abc (==p+(a+b-2p)c), final y = 2r-1.

#define C_IN 27
#define NOC 27
#define HH 32
#define WW 32
#define TILE_H 8
#define SM_ROWS (TILE_H + 2)      // 10
#define SM_W 34
#define SM_CH (SM_ROWS * SM_W)    // 340

__device__ __forceinline__ float maj3s(float a, float b, float c) {
    float p = a * b;
    float t = a + b;
    float q = fmaf(-2.0f, p, t);   // a+b-2ab
    return fmaf(q, c, p);          // ab + (a+b-2ab)c
}

__global__ __launch_bounds__(256) void sconv_kernel(const float* __restrict__ x,
                                                    const float* __restrict__ w,
                                                    float* __restrict__ out) {
    __shared__ float xs[C_IN * SM_CH];   // 27*340 floats
    __shared__ float wh[C_IN * 9];       // 0.5*weight row for this oc

    int b = blockIdx.x;
    int tile = b & 3;                 // 4 row-tiles per (n,oc)
    int oc = (b >> 2) % NOC;
    int n = b / (4 * NOC);
    int h0 = tile * TILE_H;

    int tid = threadIdx.x;

    // weights for this oc, pre-scaled by 0.5
    if (tid < C_IN * 9) {
        wh[tid] = 0.5f * w[oc * (C_IN * 9) + tid];
    }

    // stage x tile (27 ch x 10 rows x 34 cols) with pad value -1
    const float* xn = x + (size_t)n * C_IN * HH * WW;
    for (int idx = tid; idx < C_IN * SM_CH; idx += 256) {
        int c = idx / SM_CH;
        int rem = idx - c * SM_CH;
        int r = rem / SM_W;
        int col = rem - r * SM_W;
        int gh = h0 + r - 1;
        int gw = col - 1;
        float v = -1.0f;
        if ((unsigned)gh < HH && (unsigned)gw < WW)
            v = xn[(c * HH + gh) * WW + gw];
        xs[idx] = v;
    }
    __syncthreads();

    int wcol = tid & 31;       // output column 0..31
    int hl = tid >> 5;         // local row 0..7

    float v[C_IN];
    #pragma unroll
    for (int c = 0; c < C_IN; c++) {
        const float* xc = &xs[c * SM_CH + hl * SM_W + wcol];
        const float* wc = &wh[c * 9];
        float rkh[3];
        #pragma unroll
        for (int kh = 0; kh < 3; kh++) {
            float s0 = fmaf(xc[kh * SM_W + 0], wc[kh * 3 + 0], 0.5f);
            float s1 = fmaf(xc[kh * SM_W + 1], wc[kh * 3 + 1], 0.5f);
            float s2 = fmaf(xc[kh * SM_W + 2], wc[kh * 3 + 2], 0.5f);
            rkh[kh] = maj3s(s0, s1, s2);
        }
        v[c] = maj3s(rkh[0], rkh[1], rkh[2]);
    }

    // 3-level majority tree over the 27 channel values
    float u[9];
    #pragma unroll
    for (int i = 0; i < 9; i++) u[i] = maj3s(v[3 * i], v[3 * i + 1], v[3 * i + 2]);
    float t0 = maj3s(u[0], u[1], u[2]);
    float t1 = maj3s(u[3], u[4], u[5]);
    float t2 = maj3s(u[6], u[7], u[8]);
    float rr = maj3s(t0, t1, t2);
    float y = fmaf(2.0f, rr, -1.0f);

    int hg = h0 + hl;
    out[(((size_t)n * NOC + oc) * HH + hg) * WW + wcol] = y;
}

extern "C" void kernel_launch(void* const* d_in, const int* in_sizes, int n_in,
                              void* d_out, int out_size) {
    const float* x = (const float*)d_in[0];     // (8,27,32,32) fp32
    const float* w = (const float*)d_in[1];     // (27,27,3,3) fp32
    float* out = (float*)d_out;                 // (8,27,32,32) fp32

    dim3 grid(8 * NOC * 4);   // n * oc * row-tiles = 864 blocks
    sconv_kernel<<<grid, 256>>>(x, w, out);
}

// round 4
// speedup vs baseline: 1.5724x; 1.5724x over previous
#include <cuda_runtime.h>

// SConv2d majority-gate conv, s-domain math.
// R3: OCG=3 output channels per block (amortize x staging + x-LDS 3x),
//     float4 weight loads from padded smem, shift/mask staging indexing.

#define C_IN 27
#define NOC 27
#define HH 32
#define WW 32
#define TILE_H 8
#define SM_ROWS (TILE_H + 2)      // 10
#define SM_W 34
#define SM_CH (SM_ROWS * SM_W)    // 340
#define OCG 3                      // ocs per block
#define WPAD 12                    // padded weights per (oc,c): 9 -> 12 floats

__device__ __forceinline__ float maj3s(float a, float b, float c) {
    float p = a * b;
    float t = a + b;
    float q = fmaf(-2.0f, p, t);   // a+b-2ab
    return fmaf(q, c, p);          // ab + (a+b-2ab)c
}

__global__ __launch_bounds__(256) void sconv_kernel(const float* __restrict__ x,
                                                    const float* __restrict__ w,
                                                    float* __restrict__ out) {
    __shared__ float xs[C_IN * SM_CH];            // 36720 B
    __shared__ float wsm[OCG * C_IN * WPAD];      // 3*27*12*4 = 3888 B

    int b = blockIdx.x;
    int ocg  = b % (NOC / OCG);       // 0..8
    int tile = (b / (NOC / OCG)) & 3; // 0..3
    int n    = b / (4 * (NOC / OCG)); // 0..7
    int h0 = tile * TILE_H;
    int oc0 = ocg * OCG;

    int tid = threadIdx.x;

    // ---- stage weights: 3 ocs x 27 ch x 9, pre-scaled by 0.5, padded stride 12
    for (int idx = tid; idx < OCG * C_IN * 9; idx += 256) {
        int ocl = idx / (C_IN * 9);
        int rem = idx - ocl * (C_IN * 9);
        int c = rem / 9;
        int k = rem - c * 9;
        wsm[(ocl * C_IN + c) * WPAD + k] = 0.5f * w[(oc0 + ocl) * (C_IN * 9) + rem];
    }

    // ---- stage x tile interior: coalesced 32-wide rows, shift/mask indexing
    const float* xn = x + (size_t)n * C_IN * HH * WW;
    for (int idx = tid; idx < C_IN * SM_ROWS * 32; idx += 256) {
        int rowid = idx >> 5;           // c*10 + r
        int col   = idx & 31;
        int c = rowid / SM_ROWS;        // /10 -> mul-shift
        int r = rowid - c * SM_ROWS;
        int gh = h0 + r - 1;
        float v = -1.0f;
        if ((unsigned)gh < HH)
            v = xn[(c << 10) + (gh << 5) + col];
        xs[c * SM_CH + r * SM_W + col + 1] = v;
    }
    // border columns (pad value -1)
    for (int idx = tid; idx < C_IN * SM_ROWS; idx += 256) {
        xs[idx * SM_W + 0] = -1.0f;
        xs[idx * SM_W + SM_W - 1] = -1.0f;
    }
    __syncthreads();

    int wcol = tid & 31;       // output column 0..31
    int hl = tid >> 5;         // local row 0..7

    const float* xbase = &xs[hl * SM_W + wcol];

    float vbuf[OCG][3], ubuf[OCG][3], tbuf[OCG][3];

    #pragma unroll
    for (int c = 0; c < C_IN; c++) {
        // x window: 9 regs, one LDS each (imm offsets from xbase)
        float xw[9];
        #pragma unroll
        for (int kh = 0; kh < 3; kh++)
            #pragma unroll
            for (int kw = 0; kw < 3; kw++)
                xw[kh * 3 + kw] = xbase[c * SM_CH + kh * SM_W + kw];

        #pragma unroll
        for (int o = 0; o < OCG; o++) {
            const float4* wp = (const float4*)&wsm[(o * C_IN + c) * WPAD];
            float4 wa = wp[0];
            float4 wb = wp[1];
            float wk[9] = {wa.x, wa.y, wa.z, wa.w, wb.x, wb.y, wb.z, wb.w,
                           wsm[(o * C_IN + c) * WPAD + 8]};
            float rkh[3];
            #pragma unroll
            for (int kh = 0; kh < 3; kh++) {
                float s0 = fmaf(xw[kh * 3 + 0], wk[kh * 3 + 0], 0.5f);
                float s1 = fmaf(xw[kh * 3 + 1], wk[kh * 3 + 1], 0.5f);
                float s2 = fmaf(xw[kh * 3 + 2], wk[kh * 3 + 2], 0.5f);
                rkh[kh] = maj3s(s0, s1, s2);
            }
            vbuf[o][c % 3] = maj3s(rkh[0], rkh[1], rkh[2]);
        }

        if (c % 3 == 2) {
            int g = c / 3;             // 0..8
            #pragma unroll
            for (int o = 0; o < OCG; o++)
                ubuf[o][g % 3] = maj3s(vbuf[o][0], vbuf[o][1], vbuf[o][2]);
            if (g % 3 == 2) {
                #pragma unroll
                for (int o = 0; o < OCG; o++)
                    tbuf[o][g / 3] = maj3s(ubuf[o][0], ubuf[o][1], ubuf[o][2]);
            }
        }
    }

    int hg = h0 + hl;
    #pragma unroll
    for (int o = 0; o < OCG; o++) {
        float rr = maj3s(tbuf[o][0], tbuf[o][1], tbuf[o][2]);
        float y = fmaf(2.0f, rr, -1.0f);
        out[(((size_t)n * NOC + (oc0 + o)) * HH + hg) * WW + wcol] = y;
    }
}

extern "C" void kernel_launch(void* const* d_in, const int* in_sizes, int n_in,
                              void* d_out, int out_size) {
    const float* x = (const float*)d_in[0];     // (8,27,32,32) fp32
    const float* w = (const float*)d_in[1];     // (27,27,3,3) fp32
    float* out = (float*)d_out;                 // (8,27,32,32) fp32

    dim3 grid(8 * 4 * (NOC / OCG));   // n * tiles * oc-groups = 288 blocks
    sconv_kernel<<<grid, 256>>>(x, w, out);
}